// round 3
// baseline (speedup 1.0000x reference)
#include <cuda_runtime.h>
#include <cstdint>
#include <cstdio>

#define Bsz 128
#define Tsz 1024
#define Dsz 256
#define Hsz 256
#define WPAD 260   // 260 % 32 == 4 -> conflict-free LDS.128 phases, 16B aligned rows

typedef unsigned long long u64;

// Scratch for x_proj = obs @ Wi + bi  : [B*T, 768] fp32
__device__ float g_xproj[(size_t)Bsz * Tsz * 3 * Hsz];
// done dtype mode: 0 = int32 per element, 1 = uint8 per element (monotone OR)
__device__ int g_done_mode;

// packed fp32x2 FMA: d = a*b + d (two independent correctly-rounded fp32 FMAs)
__device__ __forceinline__ void ffma2(u64& d, u64 a, u64 b) {
    asm("fma.rn.f32x2 %0, %1, %2, %0;" : "+l"(d) : "l"(a), "l"(b));
}
__device__ __forceinline__ u64 pack2(float x) {
    unsigned int u = __float_as_uint(x);
    u64 r;
    asm("mov.b64 %0, {%1, %1};" : "=l"(r) : "r"(u));
    return r;
}
__device__ __forceinline__ float hsum2(u64 v) {
    float2 f = *reinterpret_cast<float2*>(&v);
    return f.x + f.y;
}

// ---------------------------------------------------------------------------
// Kernel 0: detect done dtype (int32 words of a bool array are all 0/1).
// 32768 words valid under both interpretations. atomicOr is monotone ->
// deterministic across graph replays.
// ---------------------------------------------------------------------------
__global__ void detect_done_kernel(const unsigned int* __restrict__ done_words)
{
    int i = blockIdx.x * blockDim.x + threadIdx.x;   // grid 128 x 256 = 32768
    if (done_words[i] > 1u) atomicOr(&g_done_mode, 1);
}

// ---------------------------------------------------------------------------
// Kernel 1: x_proj SGEMM (M=131072, N=768, K=256), 128x128 tiles, BK=8, FFMA2
// ---------------------------------------------------------------------------
__global__ void __launch_bounds__(256) xproj_kernel(const float* __restrict__ obs,
                                                    const float* __restrict__ Wi,
                                                    const float* __restrict__ bi)
{
    __shared__ float As[8][128];
    __shared__ float Bs[8][128];

    const int bM = blockIdx.y * 128;
    const int bN = blockIdx.x * 128;
    const int tid = threadIdx.x;
    const int tx = tid & 15;         // N
    const int ty = tid >> 4;         // M
    const int cRow = ty * 8;
    const int cCol = tx * 8;

    const int arow = tid >> 1;
    const int acol = (tid & 1) * 4;
    const int brow = tid >> 5;
    const int bcol = (tid & 31) * 4;

    const float* aptr = obs + (size_t)(bM + arow) * Dsz + acol;
    const float* bptr = Wi + (size_t)brow * 768 + bN + bcol;

    u64 acc[8][4];
#pragma unroll
    for (int i = 0; i < 8; i++)
#pragma unroll
        for (int j = 0; j < 4; j++) acc[i][j] = 0ull;

    for (int k0 = 0; k0 < Dsz; k0 += 8) {
        float4 av = *(const float4*)(aptr + k0);
        As[acol + 0][arow] = av.x;
        As[acol + 1][arow] = av.y;
        As[acol + 2][arow] = av.z;
        As[acol + 3][arow] = av.w;
        float4 bv = *(const float4*)(bptr + (size_t)k0 * 768);
        *(float4*)&Bs[brow][bcol] = bv;
        __syncthreads();

#pragma unroll
        for (int k = 0; k < 8; k++) {
            float ra[8];
            u64 rb[4];
            *(float4*)(ra)     = *(const float4*)&As[k][cRow];
            *(float4*)(ra + 4) = *(const float4*)&As[k][cRow + 4];
            {
                const u64* bsrc = (const u64*)&Bs[k][cCol];
                rb[0] = bsrc[0]; rb[1] = bsrc[1]; rb[2] = bsrc[2]; rb[3] = bsrc[3];
            }
#pragma unroll
            for (int i = 0; i < 8; i++) {
                u64 rp = pack2(ra[i]);
#pragma unroll
                for (int j = 0; j < 4; j++) ffma2(acc[i][j], rp, rb[j]);
            }
        }
        __syncthreads();
    }

    float bload[8];
    *(float4*)(bload)     = *(const float4*)(bi + bN + cCol);
    *(float4*)(bload + 4) = *(const float4*)(bi + bN + cCol + 4);
#pragma unroll
    for (int i = 0; i < 8; i++) {
        float* orow = g_xproj + (size_t)(bM + cRow + i) * 768 + bN + cCol;
        float o[8];
#pragma unroll
        for (int j = 0; j < 4; j++) {
            float2 v = *reinterpret_cast<float2*>(&acc[i][j]);
            o[2 * j]     = v.x + bload[2 * j];
            o[2 * j + 1] = v.y + bload[2 * j + 1];
        }
        *(float4*)(orow)     = *(float4*)(o);
        *(float4*)(orow + 4) = *(float4*)(o + 4);
    }
}

// ---------------------------------------------------------------------------
// Kernel 2: GRU scan. 32 clusters x 4 CTAs. Cluster c owns batches [4c,4c+4).
// CTA rank owns H-cols [rank*64, rank*64+64); weight slice [192 cols x 256 K]
// in SMEM. Thread = (c0 = tid>>2 in [0,64), g = tid&3): computes full K=256
// dots for its r/z/n columns of batch g via FFMA2, then the elementwise GRU
// update for output (g, rank*64+c0). h exchanged via st.shared::cluster.
// ---------------------------------------------------------------------------
__device__ __forceinline__ float fsigmoid(float x) {
    return __fdividef(1.f, 1.f + __expf(-x));
}
__device__ __forceinline__ float ftanh(float x) {
    return __fdividef(2.f, 1.f + __expf(-2.f * x)) - 1.f;
}

extern __shared__ float smem[];

__global__ void __launch_bounds__(256, 1) __cluster_dims__(4, 1, 1)
scan_kernel(const void* __restrict__ done_raw,
            const float* __restrict__ init_h,
            const float* __restrict__ Wh_rz,
            const float* __restrict__ Wh_n,
            const float* __restrict__ bh_n,
            float* __restrict__ out)
{
    float* W_s  = smem;                  // [192][WPAD]
    float* hbuf = W_s + 192 * WPAD;      // [2][4][256]

    const int tid  = threadIdx.x;
    const int rank = blockIdx.x & 3;
    const int cl   = blockIdx.x >> 2;
    const int b0   = cl * 4;

    const int done_mode = g_done_mode;   // 0: int32, 1: uint8
    const int* done_i32 = (const int*)done_raw;
    const unsigned char* done_u8 = (const unsigned char*)done_raw;

    // --- load weight slice (transposed into [col][k], pad WPAD) ---
    for (int idx = tid; idx < 192 * 256; idx += 256) {
        int k = idx / 192;
        int c = idx - k * 192;
        float v;
        if (c < 128) {
            int scol = (c < 64) ? (rank * 64 + c) : (256 + rank * 64 + (c - 64));
            v = Wh_rz[(size_t)k * 512 + scol];
        } else {
            v = Wh_n[(size_t)k * 256 + rank * 64 + (c - 128)];
        }
        W_s[c * WPAD + k] = v;
    }
    // --- init h phase 0 ---
    for (int idx = tid; idx < 4 * 256; idx += 256)
        hbuf[idx] = init_h[(size_t)(b0 + (idx >> 8)) * Hsz + (idx & 255)];
    __syncthreads();

    const int c0 = tid >> 2;     // 0..63 : output col within rank slice
    const int g  = tid & 3;      // 0..3  : batch within cluster
    const int jg = rank * 64 + c0;
    const float bhn = bh_n[jg];

    const ulonglong2* w0 = (const ulonglong2*)(W_s + c0 * WPAD);
    const ulonglong2* w1 = (const ulonglong2*)(W_s + (c0 + 64) * WPAD);
    const ulonglong2* w2 = (const ulonglong2*)(W_s + (c0 + 128) * WPAD);

    uint32_t hbuf_u32;
    asm("{ .reg .u64 t; cvta.to.shared.u64 t, %1; cvt.u32.u64 %0, t; }"
        : "=r"(hbuf_u32) : "l"(hbuf));

    const size_t done_base = (size_t)(b0 + g) * Tsz;
    const size_t x_base = (size_t)(b0 + g) * Tsz * 768 + jg;
    float* ys = out + Bsz * Hsz;
    int p = 0;

    for (int t = 0; t < Tsz; t++) {
        // prefetch this step's x slice + done flag (latency hidden by dots)
        const float* xp = g_xproj + x_base + (size_t)t * 768;
        float xr = __ldg(xp);
        float xz = __ldg(xp + 256);
        float xn = __ldg(xp + 512);
        int dn = done_mode ? (int)done_u8[done_base + t] : done_i32[done_base + t];

        const float* hrow = hbuf + p * 1024 + g * 256;
        float hcur = hrow[jg];

        // dots: 3 cols x K=256 against batch g's h, packed fp32x2
        const ulonglong2* hb = (const ulonglong2*)hrow;
        u64 a00 = 0, a01 = 0, a10 = 0, a11 = 0, a20 = 0, a21 = 0;
#pragma unroll 8
        for (int kq = 0; kq < 64; kq++) {
            ulonglong2 h = hb[kq];
            ulonglong2 x0 = w0[kq];
            ffma2(a00, x0.x, h.x); ffma2(a01, x0.y, h.y);
            ulonglong2 x1 = w1[kq];
            ffma2(a10, x1.x, h.x); ffma2(a11, x1.y, h.y);
            ulonglong2 x2 = w2[kq];
            ffma2(a20, x2.x, h.x); ffma2(a21, x2.y, h.y);
        }
        float hr = hsum2(a00) + hsum2(a01);
        float hz = hsum2(a10) + hsum2(a11);
        float hn = hsum2(a20) + hsum2(a21);

        if (dn) { hr = 0.f; hz = 0.f; hn = 0.f; hcur = 0.f; }
        float r = fsigmoid(xr + hr);
        float z = fsigmoid(xz + hz);
        float n = ftanh(xn + r * (hn + bhn));
        float hnew = n + z * (hcur - n);

        ys[((size_t)(b0 + g) * Tsz + t) * Hsz + jg] = hnew;
        if (t == Tsz - 1) out[(b0 + g) * Hsz + jg] = hnew;

        // broadcast h_new into all 4 cluster CTAs' next-phase buffer
        uint32_t la = hbuf_u32 + (uint32_t)(((1 - p) * 1024 + g * 256 + jg) * 4);
#pragma unroll
        for (uint32_t dst = 0; dst < 4; dst++) {
            uint32_t ra;
            asm volatile("mapa.shared::cluster.u32 %0, %1, %2;"
                         : "=r"(ra) : "r"(la), "r"(dst));
            asm volatile("st.shared::cluster.f32 [%0], %1;"
                         :: "r"(ra), "f"(hnew) : "memory");
        }

        asm volatile("barrier.cluster.arrive.aligned;" ::: "memory");
        asm volatile("barrier.cluster.wait.aligned;" ::: "memory");
        p ^= 1;
    }
}

// ---------------------------------------------------------------------------
// Launch
// ---------------------------------------------------------------------------
static const int SCAN_SMEM_BYTES = (192 * WPAD + 2 * 4 * 256) * 4;

extern "C" void kernel_launch(void* const* d_in, const int* in_sizes, int n_in,
                              void* d_out, int out_size)
{
    (void)in_sizes; (void)n_in; (void)out_size;
    const float* obs    = (const float*)d_in[0];
    const void*  done   = d_in[1];
    const float* init_h = (const float*)d_in[2];
    const float* Wi     = (const float*)d_in[3];
    const float* bi     = (const float*)d_in[4];
    const float* Wh_rz  = (const float*)d_in[5];
    const float* Wh_n   = (const float*)d_in[6];
    const float* bh_n   = (const float*)d_in[7];
    float* out = (float*)d_out;

    cudaFuncSetAttribute(scan_kernel, cudaFuncAttributeMaxDynamicSharedMemorySize,
                         SCAN_SMEM_BYTES);

    detect_done_kernel<<<128, 256>>>((const unsigned int*)done);

    dim3 ggrid(768 / 128, (Bsz * Tsz) / 128);  // (6, 1024)
    xproj_kernel<<<ggrid, 256>>>(obs, Wi, bi);

    scan_kernel<<<128, 256, SCAN_SMEM_BYTES>>>(done, init_h, Wh_rz, Wh_n, bh_n, out);
}

// round 4
// speedup vs baseline: 1.7533x; 1.7533x over previous
#include <cuda_runtime.h>
#include <cstdint>
#include <cstdio>

#define Bsz 128
#define Tsz 1024
#define Dsz 256
#define Hsz 256
#define WPAD 260   // 260 % 32 == 4 -> conflict-free LDS.128 phases, 16B aligned rows

typedef unsigned long long u64;

// Scratch for x_proj = obs @ Wi + bi  : [B*T, 768] fp32
__device__ float g_xproj[(size_t)Bsz * Tsz * 3 * Hsz];
// done dtype mode: 0 = int32 per element, 1 = uint8 per element (monotone OR)
__device__ int g_done_mode;

// packed fp32x2 FMA: d = a*b + d (two independent correctly-rounded fp32 FMAs)
__device__ __forceinline__ void ffma2(u64& d, u64 a, u64 b) {
    asm("fma.rn.f32x2 %0, %1, %2, %0;" : "+l"(d) : "l"(a), "l"(b));
}
__device__ __forceinline__ float hsum2(u64 v) {
    float2 f = *reinterpret_cast<float2*>(&v);
    return f.x + f.y;
}

// ---------------------------------------------------------------------------
// Kernel 0: detect done dtype (int32 words of a bool array are all 0/1).
// ---------------------------------------------------------------------------
__global__ void detect_done_kernel(const unsigned int* __restrict__ done_words)
{
    int i = blockIdx.x * blockDim.x + threadIdx.x;   // 128 x 256 = 32768 words
    if (done_words[i] > 1u) atomicOr(&g_done_mode, 1);
}

// ---------------------------------------------------------------------------
// Kernel 1: x_proj SGEMM (M=131072, N=768, K=256), 128x128 tiles, BK=8
// (exact R2 known-good version, plain FFMA)
// ---------------------------------------------------------------------------
__global__ void __launch_bounds__(256) xproj_kernel(const float* __restrict__ obs,
                                                    const float* __restrict__ Wi,
                                                    const float* __restrict__ bi)
{
    __shared__ float As[8][128];
    __shared__ float Bs[8][128];

    const int bM = blockIdx.y * 128;
    const int bN = blockIdx.x * 128;
    const int tid = threadIdx.x;
    const int tx = tid & 15;
    const int ty = tid >> 4;
    const int cRow = ty * 8;
    const int cCol = tx * 8;

    const int arow = tid >> 1;
    const int acol = (tid & 1) * 4;
    const int brow = tid >> 5;
    const int bcol = (tid & 31) * 4;

    const float* aptr = obs + (size_t)(bM + arow) * Dsz + acol;
    const float* bptr = Wi + (size_t)brow * 768 + bN + bcol;

    float acc[8][8];
#pragma unroll
    for (int i = 0; i < 8; i++)
#pragma unroll
        for (int j = 0; j < 8; j++) acc[i][j] = 0.f;

    for (int k0 = 0; k0 < Dsz; k0 += 8) {
        float4 av = *(const float4*)(aptr + k0);
        As[acol + 0][arow] = av.x;
        As[acol + 1][arow] = av.y;
        As[acol + 2][arow] = av.z;
        As[acol + 3][arow] = av.w;
        float4 bv = *(const float4*)(bptr + (size_t)k0 * 768);
        *(float4*)&Bs[brow][bcol] = bv;
        __syncthreads();

#pragma unroll
        for (int k = 0; k < 8; k++) {
            float ra[8], rb[8];
            *(float4*)(ra)     = *(const float4*)&As[k][cRow];
            *(float4*)(ra + 4) = *(const float4*)&As[k][cRow + 4];
            *(float4*)(rb)     = *(const float4*)&Bs[k][cCol];
            *(float4*)(rb + 4) = *(const float4*)&Bs[k][cCol + 4];
#pragma unroll
            for (int i = 0; i < 8; i++)
#pragma unroll
                for (int j = 0; j < 8; j++)
                    acc[i][j] = fmaf(ra[i], rb[j], acc[i][j]);
        }
        __syncthreads();
    }

    float4 b0 = *(const float4*)(bi + bN + cCol);
    float4 b1 = *(const float4*)(bi + bN + cCol + 4);
#pragma unroll
    for (int i = 0; i < 8; i++) {
        float* orow = g_xproj + (size_t)(bM + cRow + i) * 768 + bN + cCol;
        float4 o0 = make_float4(acc[i][0] + b0.x, acc[i][1] + b0.y,
                                acc[i][2] + b0.z, acc[i][3] + b0.w);
        float4 o1 = make_float4(acc[i][4] + b1.x, acc[i][5] + b1.y,
                                acc[i][6] + b1.z, acc[i][7] + b1.w);
        *(float4*)(orow)     = o0;
        *(float4*)(orow + 4) = o1;
    }
}

// ---------------------------------------------------------------------------
// Kernel 2: GRU scan — R2 layout (192 dot threads, broadcast h, smem accs),
// ONLY change vs R2: inner dot uses packed fp32x2 FMAs.
// ---------------------------------------------------------------------------
__device__ __forceinline__ float fsigmoid(float x) {
    return __fdividef(1.f, 1.f + __expf(-x));
}
__device__ __forceinline__ float ftanh(float x) {
    return __fdividef(2.f, 1.f + __expf(-2.f * x)) - 1.f;
}

extern __shared__ float smem[];

__global__ void __launch_bounds__(256, 1) __cluster_dims__(4, 1, 1)
scan_kernel(const void* __restrict__ done_raw,
            const float* __restrict__ init_h,
            const float* __restrict__ Wh_rz,
            const float* __restrict__ Wh_n,
            const float* __restrict__ bh_n,
            float* __restrict__ out)
{
    // SMEM layout (floats):
    float* W_s   = smem;                       // [192][WPAD]
    float* hbuf  = W_s + 192 * WPAD;           // [2][4][256]
    float* xs    = hbuf + 2 * 4 * 256;         // [4][192]
    float* accs  = xs + 4 * 192;               // [192][4]
    float* bhn_s = accs + 192 * 4;             // [64]
    int*   done_s = (int*)(bhn_s + 64);        // [4]

    const int tid  = threadIdx.x;
    const int rank = blockIdx.x & 3;
    const int cl   = blockIdx.x >> 2;
    const int b0   = cl * 4;

    const int done_mode = g_done_mode;   // 0: int32, 1: uint8
    const int* done_i32 = (const int*)done_raw;
    const unsigned char* done_u8 = (const unsigned char*)done_raw;

    // --- load weight slice (transposed into [col][k], pad WPAD) ---
    for (int idx = tid; idx < 192 * 256; idx += 256) {
        int k = idx / 192;
        int c = idx - k * 192;
        float v;
        if (c < 128) {
            int scol = (c < 64) ? (rank * 64 + c) : (256 + rank * 64 + (c - 64));
            v = Wh_rz[(size_t)k * 512 + scol];
        } else {
            v = Wh_n[(size_t)k * 256 + rank * 64 + (c - 128)];
        }
        W_s[c * WPAD + k] = v;
    }
    if (tid < 64) bhn_s[tid] = bh_n[rank * 64 + tid];

    // --- init h phase 0 ---
    for (int idx = tid; idx < 4 * 256; idx += 256)
        hbuf[idx] = init_h[(size_t)(b0 + (idx >> 8)) * Hsz + (idx & 255)];
    __syncthreads();

    uint32_t hbuf_u32;
    asm("{ .reg .u64 t; cvta.to.shared.u64 t, %1; cvt.u32.u64 %0, t; }"
        : "=r"(hbuf_u32) : "l"(hbuf));

    float* ys = out + Bsz * Hsz;
    int p = 0;

    for (int t = 0; t < Tsz; t++) {
        if (tid < 192) {
            // dot products: 192 columns x 4 batches, K=256, packed fp32x2
            const ulonglong2* Wc = (const ulonglong2*)(W_s + tid * WPAD);
            const ulonglong2* hb = (const ulonglong2*)(hbuf + p * 1024);
            u64 a0l = 0, a0h = 0, a1l = 0, a1h = 0;
            u64 a2l = 0, a2h = 0, a3l = 0, a3h = 0;
#pragma unroll 4
            for (int kq = 0; kq < 64; kq++) {
                ulonglong2 w  = Wc[kq];              // w[4k..4k+3] unique row
                ulonglong2 h0 = hb[kq];              // broadcast loads
                ffma2(a0l, w.x, h0.x); ffma2(a0h, w.y, h0.y);
                ulonglong2 h1 = hb[64 + kq];
                ffma2(a1l, w.x, h1.x); ffma2(a1h, w.y, h1.y);
                ulonglong2 h2 = hb[128 + kq];
                ffma2(a2l, w.x, h2.x); ffma2(a2h, w.y, h2.y);
                ulonglong2 h3 = hb[192 + kq];
                ffma2(a3l, w.x, h3.x); ffma2(a3h, w.y, h3.y);
            }
            ((float4*)accs)[tid] = make_float4(hsum2(a0l) + hsum2(a0h),
                                               hsum2(a1l) + hsum2(a1h),
                                               hsum2(a2l) + hsum2(a2h),
                                               hsum2(a3l) + hsum2(a3h));
        } else {
            // prefetch x_proj slice + done flags for this step
            int lt = tid - 192;
            if (lt < 4) {
                size_t di = (size_t)(b0 + lt) * Tsz + t;
                done_s[lt] = done_mode ? (int)done_u8[di] : done_i32[di];
            }
            for (int i = lt; i < 768; i += 64) {
                int g = i / 192;
                int c = i - g * 192;
                int col = (c < 64) ? (rank * 64 + c)
                        : (c < 128) ? (256 + rank * 64 + (c - 64))
                                    : (512 + rank * 64 + (c - 128));
                xs[g * 192 + c] = g_xproj[((size_t)(b0 + g) * Tsz + t) * 768 + col];
            }
        }
        __syncthreads();

        {
            const int g  = tid >> 6;
            const int j  = tid & 63;
            const int jg = rank * 64 + j;
            float hr = accs[j * 4 + g];
            float hz = accs[(64 + j) * 4 + g];
            float hn = accs[(128 + j) * 4 + g];
            float hcur = hbuf[p * 1024 + g * 256 + jg];
            if (done_s[g]) { hr = 0.f; hz = 0.f; hn = 0.f; hcur = 0.f; }
            float r = fsigmoid(xs[g * 192 + j] + hr);
            float z = fsigmoid(xs[g * 192 + 64 + j] + hz);
            float n = ftanh(xs[g * 192 + 128 + j] + r * (hn + bhn_s[j]));
            float hnew = n + z * (hcur - n);

            ys[((size_t)(b0 + g) * Tsz + t) * Hsz + jg] = hnew;
            if (t == Tsz - 1) out[(b0 + g) * Hsz + jg] = hnew;

            // broadcast h_new to all 4 cluster CTAs' next-phase buffer
            uint32_t la = hbuf_u32 + (uint32_t)(((1 - p) * 1024 + g * 256 + jg) * 4);
#pragma unroll
            for (uint32_t dst = 0; dst < 4; dst++) {
                uint32_t ra;
                asm volatile("mapa.shared::cluster.u32 %0, %1, %2;"
                             : "=r"(ra) : "r"(la), "r"(dst));
                asm volatile("st.shared::cluster.f32 [%0], %1;"
                             :: "r"(ra), "f"(hnew) : "memory");
            }
        }

        asm volatile("barrier.cluster.arrive.aligned;" ::: "memory");
        asm volatile("barrier.cluster.wait.aligned;" ::: "memory");
        p ^= 1;
    }
}

// ---------------------------------------------------------------------------
// Launch
// ---------------------------------------------------------------------------
static const int SCAN_SMEM_BYTES =
    (192 * WPAD + 2 * 4 * 256 + 4 * 192 + 192 * 4 + 64 + 4) * 4;

extern "C" void kernel_launch(void* const* d_in, const int* in_sizes, int n_in,
                              void* d_out, int out_size)
{
    (void)in_sizes; (void)n_in; (void)out_size;
    const float* obs    = (const float*)d_in[0];
    const void*  done   = d_in[1];
    const float* init_h = (const float*)d_in[2];
    const float* Wi     = (const float*)d_in[3];
    const float* bi     = (const float*)d_in[4];
    const float* Wh_rz  = (const float*)d_in[5];
    const float* Wh_n   = (const float*)d_in[6];
    const float* bh_n   = (const float*)d_in[7];
    float* out = (float*)d_out;

    cudaFuncSetAttribute(scan_kernel, cudaFuncAttributeMaxDynamicSharedMemorySize,
                         SCAN_SMEM_BYTES);

    detect_done_kernel<<<128, 256>>>((const unsigned int*)done);

    dim3 ggrid(768 / 128, (Bsz * Tsz) / 128);  // (6, 1024)
    xproj_kernel<<<ggrid, 256>>>(obs, Wi, bi);

    scan_kernel<<<128, 256, SCAN_SMEM_BYTES>>>(done, init_h, Wh_rz, Wh_n, bh_n, out);
}

// round 6
// speedup vs baseline: 2.0225x; 1.1535x over previous
#include <cuda_runtime.h>
#include <cuda_bf16.h>
#include <cstdint>

#define Bsz 128
#define Tsz 1024
#define Dsz 256
#define Hsz 256
#define WPAD 260

typedef unsigned long long u64;

// ---------------- scratch (__device__ globals; no runtime alloc) ----------
__device__ float g_xproj[(size_t)Bsz * Tsz * 3 * Hsz];          // [B*T,768]
__device__ __nv_bfloat16 g_a_hi[(size_t)Bsz * Tsz * Dsz];       // obs hi
__device__ __nv_bfloat16 g_a_lo[(size_t)Bsz * Tsz * Dsz];       // obs lo
__device__ __nv_bfloat16 g_wt_hi[768 * 256];                    // Wi^T hi [n][k]
__device__ __nv_bfloat16 g_wt_lo[768 * 256];                    // Wi^T lo
__device__ int g_done_mode;

// packed fp32x2 FMA (scan only)
__device__ __forceinline__ void ffma2(u64& d, u64 a, u64 b) {
    asm("fma.rn.f32x2 %0, %1, %2, %0;" : "+l"(d) : "l"(a), "l"(b));
}
__device__ __forceinline__ float hsum2(u64 v) {
    float2 f = *reinterpret_cast<float2*>(&v);
    return f.x + f.y;
}
__device__ __forceinline__ uint32_t smem_u32(const void* p) {
    uint32_t a;
    asm("{ .reg .u64 t; cvta.to.shared.u64 t, %1; cvt.u32.u64 %0, t; }"
        : "=r"(a) : "l"(p));
    return a;
}
__device__ __forceinline__ void cp16(uint32_t s, const void* g) {
    asm volatile("cp.async.cg.shared.global [%0], [%1], 16;"
                 :: "r"(s), "l"(__cvta_generic_to_global(g)) : "memory");
}
#define LDSM4(r, addr) \
    asm volatile("ldmatrix.sync.aligned.m8n8.x4.shared.b16 {%0,%1,%2,%3}, [%4];" \
                 : "=r"((r)[0]), "=r"((r)[1]), "=r"((r)[2]), "=r"((r)[3]) : "r"(addr))
#define MMA(c, A, b0, b1) \
    asm volatile("mma.sync.aligned.m16n8k16.row.col.f32.bf16.bf16.f32 " \
                 "{%0,%1,%2,%3},{%4,%5,%6,%7},{%8,%9},{%0,%1,%2,%3};" \
                 : "+f"((c)[0]), "+f"((c)[1]), "+f"((c)[2]), "+f"((c)[3]) \
                 : "r"((A)[0]), "r"((A)[1]), "r"((A)[2]), "r"((A)[3]), \
                   "r"(b0), "r"(b1))

// ---------------------------------------------------------------------------
// Kernel 0: detect done dtype
// ---------------------------------------------------------------------------
__global__ void detect_done_kernel(const unsigned int* __restrict__ done_words)
{
    int i = blockIdx.x * blockDim.x + threadIdx.x;   // 32768 words
    if (done_words[i] > 1u) atomicOr(&g_done_mode, 1);
}

// ---------------------------------------------------------------------------
// Kernel A: decompose obs into bf16 hi/lo
// ---------------------------------------------------------------------------
__global__ void decompose_obs(const float* __restrict__ src)
{
    size_t i = (size_t)blockIdx.x * blockDim.x + threadIdx.x;  // 8388608 float4
    float4 v = ((const float4*)src)[i];
    __nv_bfloat16 h0 = __float2bfloat16(v.x);
    __nv_bfloat16 h1 = __float2bfloat16(v.y);
    __nv_bfloat16 h2 = __float2bfloat16(v.z);
    __nv_bfloat16 h3 = __float2bfloat16(v.w);
    __nv_bfloat16 l0 = __float2bfloat16(v.x - __bfloat162float(h0));
    __nv_bfloat16 l1 = __float2bfloat16(v.y - __bfloat162float(h1));
    __nv_bfloat16 l2 = __float2bfloat16(v.z - __bfloat162float(h2));
    __nv_bfloat16 l3 = __float2bfloat16(v.w - __bfloat162float(h3));
    __nv_bfloat162* hp = (__nv_bfloat162*)g_a_hi;
    __nv_bfloat162* lp = (__nv_bfloat162*)g_a_lo;
    hp[2 * i]     = __nv_bfloat162(h0, h1);
    hp[2 * i + 1] = __nv_bfloat162(h2, h3);
    lp[2 * i]     = __nv_bfloat162(l0, l1);
    lp[2 * i + 1] = __nv_bfloat162(l2, l3);
}

// Kernel B: decompose + transpose Wi [256][768] -> Wi^T [768][256] hi/lo
__global__ void decompose_wi(const float* __restrict__ Wi)
{
    int idx = blockIdx.x * blockDim.x + threadIdx.x;   // 196608
    int k = idx / 768, n = idx - k * 768;
    float w = Wi[idx];
    __nv_bfloat16 h = __float2bfloat16(w);
    __nv_bfloat16 l = __float2bfloat16(w - __bfloat162float(h));
    g_wt_hi[n * 256 + k] = h;
    g_wt_lo[n * 256 + k] = l;
}

// ---------------------------------------------------------------------------
// Kernel 1: x_proj GEMM via mma.sync bf16 (hi/lo split, 3 products).
// M=131072 N=768 K=256. CTA tile 128x128, BK=32, 8 warps (4m x 2n),
// warp tile 32x64. cp.async double-buffered. Row pitch 80B (conflict-free
// ldmatrix: r*80 mod 128 covers disjoint 16B windows).
// ---------------------------------------------------------------------------
#define STAGE_B 40960
#define OFF_AHI 0
#define OFF_ALO 10240
#define OFF_BHI 20480
#define OFF_BLO 30720
#define XSMEM   (2 * STAGE_B)

__global__ void __launch_bounds__(256, 2)
xproj_mma_kernel(const float* __restrict__ bi)
{
    extern __shared__ char xsm[];
    const int tid = threadIdx.x, wid = tid >> 5, lane = tid & 31;
    const int warp_m = wid & 3, warp_n = wid >> 2;
    const int bN = blockIdx.x * 128;
    const int bM = blockIdx.y * 128;
    const uint32_t sb = smem_u32(xsm);

    // ldmatrix per-lane offsets
    const int grp = lane >> 3, r = lane & 7;
    uint32_t aoff[2], boff[4];
#pragma unroll
    for (int mt = 0; mt < 2; mt++)
        aoff[mt] = (uint32_t)((warp_m * 32 + mt * 16 + (grp & 1) * 8 + r) * 80
                              + (grp >> 1) * 16);
#pragma unroll
    for (int np = 0; np < 4; np++)
        boff[np] = (uint32_t)((warp_n * 64 + np * 16 + (grp >> 1) * 8 + r) * 80
                              + (grp & 1) * 16);

    // per-thread gmem/smem chunk coords for staging (2 chunks of 16B / matrix)
    const int c0row = tid >> 2, c0kc = tid & 3;          // chunk tid
    const int c1row = (tid + 256) >> 2, c1kc = (tid + 256) & 3;

    auto load_stage = [&](int ks, int buf) {
        const uint32_t s = sb + buf * STAGE_B;
        const int k0 = ks * 32;
        {
            uint32_t so = c0row * 80 + c0kc * 16;
            size_t ga = (size_t)(bM + c0row) * 256 + k0 + c0kc * 8;
            size_t gb = (size_t)(bN + c0row) * 256 + k0 + c0kc * 8;
            cp16(s + OFF_AHI + so, g_a_hi + ga);
            cp16(s + OFF_ALO + so, g_a_lo + ga);
            cp16(s + OFF_BHI + so, g_wt_hi + gb);
            cp16(s + OFF_BLO + so, g_wt_lo + gb);
        }
        {
            uint32_t so = c1row * 80 + c1kc * 16;
            size_t ga = (size_t)(bM + c1row) * 256 + k0 + c1kc * 8;
            size_t gb = (size_t)(bN + c1row) * 256 + k0 + c1kc * 8;
            cp16(s + OFF_AHI + so, g_a_hi + ga);
            cp16(s + OFF_ALO + so, g_a_lo + ga);
            cp16(s + OFF_BHI + so, g_wt_hi + gb);
            cp16(s + OFF_BLO + so, g_wt_lo + gb);
        }
        asm volatile("cp.async.commit_group;" ::: "memory");
    };

    float acc[2][8][4];
#pragma unroll
    for (int mt = 0; mt < 2; mt++)
#pragma unroll
        for (int nt = 0; nt < 8; nt++)
#pragma unroll
            for (int e = 0; e < 4; e++) acc[mt][nt][e] = 0.f;

    load_stage(0, 0);
    load_stage(1, 1);

#pragma unroll 1
    for (int ks = 0; ks < 8; ks++) {
        if (ks < 7)
            asm volatile("cp.async.wait_group 1;" ::: "memory");
        else
            asm volatile("cp.async.wait_group 0;" ::: "memory");
        __syncthreads();

        const uint32_t s = sb + (ks & 1) * STAGE_B;
#pragma unroll
        for (int h = 0; h < 2; h++) {
            uint32_t a[2][2][4];   // [comp][mt][4]
#pragma unroll
            for (int mt = 0; mt < 2; mt++) {
                LDSM4(a[0][mt], s + OFF_AHI + aoff[mt] + h * 32);
                LDSM4(a[1][mt], s + OFF_ALO + aoff[mt] + h * 32);
            }
#pragma unroll
            for (int np = 0; np < 4; np++) {
                uint32_t bh[4], bl[4];
                LDSM4(bh, s + OFF_BHI + boff[np] + h * 32);
                LDSM4(bl, s + OFF_BLO + boff[np] + h * 32);
#pragma unroll
                for (int mt = 0; mt < 2; mt++) {
                    MMA(acc[mt][2 * np],     a[0][mt], bh[0], bh[1]);  // hi*hi
                    MMA(acc[mt][2 * np + 1], a[0][mt], bh[2], bh[3]);
                    MMA(acc[mt][2 * np],     a[0][mt], bl[0], bl[1]);  // hi*lo
                    MMA(acc[mt][2 * np + 1], a[0][mt], bl[2], bl[3]);
                    MMA(acc[mt][2 * np],     a[1][mt], bh[0], bh[1]);  // lo*hi
                    MMA(acc[mt][2 * np + 1], a[1][mt], bh[2], bh[3]);
                }
            }
        }
        __syncthreads();
        if (ks + 2 < 8) load_stage(ks + 2, ks & 1);
    }

    // epilogue: D + bias -> g_xproj
    const int tq = lane >> 2, tr = lane & 3;
#pragma unroll
    for (int mt = 0; mt < 2; mt++) {
#pragma unroll
        for (int nt = 0; nt < 8; nt++) {
            int row = bM + warp_m * 32 + mt * 16 + tq;
            int col = bN + warp_n * 64 + nt * 8 + tr * 2;
            float2 bb = *(const float2*)(bi + col);
            float2 o0 = make_float2(acc[mt][nt][0] + bb.x, acc[mt][nt][1] + bb.y);
            float2 o1 = make_float2(acc[mt][nt][2] + bb.x, acc[mt][nt][3] + bb.y);
            *(float2*)(g_xproj + (size_t)row * 768 + col)       = o0;
            *(float2*)(g_xproj + (size_t)(row + 8) * 768 + col) = o1;
        }
    }
}

// ---------------------------------------------------------------------------
// Kernel 2: GRU scan — EXACT R4 version (untouched)
// ---------------------------------------------------------------------------
__device__ __forceinline__ float fsigmoid(float x) {
    return __fdividef(1.f, 1.f + __expf(-x));
}
__device__ __forceinline__ float ftanh(float x) {
    return __fdividef(2.f, 1.f + __expf(-2.f * x)) - 1.f;
}

extern __shared__ float smem[];

__global__ void __launch_bounds__(256, 1) __cluster_dims__(4, 1, 1)
scan_kernel(const void* __restrict__ done_raw,
            const float* __restrict__ init_h,
            const float* __restrict__ Wh_rz,
            const float* __restrict__ Wh_n,
            const float* __restrict__ bh_n,
            float* __restrict__ out)
{
    float* W_s   = smem;                       // [192][WPAD]
    float* hbuf  = W_s + 192 * WPAD;           // [2][4][256]
    float* xs    = hbuf + 2 * 4 * 256;         // [4][192]
    float* accs  = xs + 4 * 192;               // [192][4]
    float* bhn_s = accs + 192 * 4;             // [64]
    int*   done_s = (int*)(bhn_s + 64);        // [4]

    const int tid  = threadIdx.x;
    const int rank = blockIdx.x & 3;
    const int cl   = blockIdx.x >> 2;
    const int b0   = cl * 4;

    const int done_mode = g_done_mode;
    const int* done_i32 = (const int*)done_raw;
    const unsigned char* done_u8 = (const unsigned char*)done_raw;

    for (int idx = tid; idx < 192 * 256; idx += 256) {
        int k = idx / 192;
        int c = idx - k * 192;
        float v;
        if (c < 128) {
            int scol = (c < 64) ? (rank * 64 + c) : (256 + rank * 64 + (c - 64));
            v = Wh_rz[(size_t)k * 512 + scol];
        } else {
            v = Wh_n[(size_t)k * 256 + rank * 64 + (c - 128)];
        }
        W_s[c * WPAD + k] = v;
    }
    if (tid < 64) bhn_s[tid] = bh_n[rank * 64 + tid];

    for (int idx = tid; idx < 4 * 256; idx += 256)
        hbuf[idx] = init_h[(size_t)(b0 + (idx >> 8)) * Hsz + (idx & 255)];
    __syncthreads();

    uint32_t hbuf_u32 = smem_u32(hbuf);

    float* ys = out + Bsz * Hsz;
    int p = 0;

    for (int t = 0; t < Tsz; t++) {
        if (tid < 192) {
            const ulonglong2* Wc = (const ulonglong2*)(W_s + tid * WPAD);
            const ulonglong2* hb = (const ulonglong2*)(hbuf + p * 1024);
            u64 a0l = 0, a0h = 0, a1l = 0, a1h = 0;
            u64 a2l = 0, a2h = 0, a3l = 0, a3h = 0;
#pragma unroll 4
            for (int kq = 0; kq < 64; kq++) {
                ulonglong2 w  = Wc[kq];
                ulonglong2 h0 = hb[kq];
                ffma2(a0l, w.x, h0.x); ffma2(a0h, w.y, h0.y);
                ulonglong2 h1 = hb[64 + kq];
                ffma2(a1l, w.x, h1.x); ffma2(a1h, w.y, h1.y);
                ulonglong2 h2 = hb[128 + kq];
                ffma2(a2l, w.x, h2.x); ffma2(a2h, w.y, h2.y);
                ulonglong2 h3 = hb[192 + kq];
                ffma2(a3l, w.x, h3.x); ffma2(a3h, w.y, h3.y);
            }
            ((float4*)accs)[tid] = make_float4(hsum2(a0l) + hsum2(a0h),
                                               hsum2(a1l) + hsum2(a1h),
                                               hsum2(a2l) + hsum2(a2h),
                                               hsum2(a3l) + hsum2(a3h));
        } else {
            int lt = tid - 192;
            if (lt < 4) {
                size_t di = (size_t)(b0 + lt) * Tsz + t;
                done_s[lt] = done_mode ? (int)done_u8[di] : done_i32[di];
            }
            for (int i = lt; i < 768; i += 64) {
                int g = i / 192;
                int c = i - g * 192;
                int col = (c < 64) ? (rank * 64 + c)
                        : (c < 128) ? (256 + rank * 64 + (c - 64))
                                    : (512 + rank * 64 + (c - 128));
                xs[g * 192 + c] = g_xproj[((size_t)(b0 + g) * Tsz + t) * 768 + col];
            }
        }
        __syncthreads();

        {
            const int g  = tid >> 6;
            const int j  = tid & 63;
            const int jg = rank * 64 + j;
            float hr = accs[j * 4 + g];
            float hz = accs[(64 + j) * 4 + g];
            float hn = accs[(128 + j) * 4 + g];
            float hcur = hbuf[p * 1024 + g * 256 + jg];
            if (done_s[g]) { hr = 0.f; hz = 0.f; hn = 0.f; hcur = 0.f; }
            float r = fsigmoid(xs[g * 192 + j] + hr);
            float z = fsigmoid(xs[g * 192 + 64 + j] + hz);
            float n = ftanh(xs[g * 192 + 128 + j] + r * (hn + bhn_s[j]));
            float hnew = n + z * (hcur - n);

            ys[((size_t)(b0 + g) * Tsz + t) * Hsz + jg] = hnew;
            if (t == Tsz - 1) out[(b0 + g) * Hsz + jg] = hnew;

            uint32_t la = hbuf_u32 + (uint32_t)(((1 - p) * 1024 + g * 256 + jg) * 4);
#pragma unroll
            for (uint32_t dst = 0; dst < 4; dst++) {
                uint32_t ra;
                asm volatile("mapa.shared::cluster.u32 %0, %1, %2;"
                             : "=r"(ra) : "r"(la), "r"(dst));
                asm volatile("st.shared::cluster.f32 [%0], %1;"
                             :: "r"(ra), "f"(hnew) : "memory");
            }
        }

        asm volatile("barrier.cluster.arrive.aligned;" ::: "memory");
        asm volatile("barrier.cluster.wait.aligned;" ::: "memory");
        p ^= 1;
    }
}

// ---------------------------------------------------------------------------
// Launch
// ---------------------------------------------------------------------------
static const int SCAN_SMEM_BYTES =
    (192 * WPAD + 2 * 4 * 256 + 4 * 192 + 192 * 4 + 64 + 4) * 4;

extern "C" void kernel_launch(void* const* d_in, const int* in_sizes, int n_in,
                              void* d_out, int out_size)
{
    (void)in_sizes; (void)n_in; (void)out_size;
    const float* obs    = (const float*)d_in[0];
    const void*  done   = d_in[1];
    const float* init_h = (const float*)d_in[2];
    const float* Wi     = (const float*)d_in[3];
    const float* bi     = (const float*)d_in[4];
    const float* Wh_rz  = (const float*)d_in[5];
    const float* Wh_n   = (const float*)d_in[6];
    const float* bh_n   = (const float*)d_in[7];
    float* out = (float*)d_out;

    cudaFuncSetAttribute(scan_kernel, cudaFuncAttributeMaxDynamicSharedMemorySize,
                         SCAN_SMEM_BYTES);
    cudaFuncSetAttribute(xproj_mma_kernel, cudaFuncAttributeMaxDynamicSharedMemorySize,
                         XSMEM);

    detect_done_kernel<<<128, 256>>>((const unsigned int*)done);
    decompose_obs<<<32768, 256>>>(obs);
    decompose_wi<<<768, 256>>>(Wi);

    dim3 ggrid(6, 1024);   // N-tiles (x, fastest -> A reuse in L2) x M-tiles
    xproj_mma_kernel<<<ggrid, 256, XSMEM>>>(bi);

    scan_kernel<<<128, 256, SCAN_SMEM_BYTES>>>(done, init_h, Wh_rz, Wh_n, bh_n, out);
}

// round 7
// speedup vs baseline: 2.1899x; 1.0828x over previous
#include <cuda_runtime.h>
#include <cuda_bf16.h>
#include <cstdint>

#define Bsz 128
#define Tsz 1024
#define Dsz 256
#define Hsz 256
#define WPAD 260

typedef unsigned long long u64;

// ---------------- scratch (__device__ globals; no runtime alloc) ----------
__device__ float g_xproj[(size_t)Bsz * Tsz * 3 * Hsz];          // [B*T,768]
__device__ __nv_bfloat16 g_a_hi[(size_t)Bsz * Tsz * Dsz];       // obs hi
__device__ __nv_bfloat16 g_a_lo[(size_t)Bsz * Tsz * Dsz];       // obs lo
__device__ __nv_bfloat16 g_wt_hi[768 * 256];                    // Wi^T hi [n][k]
__device__ __nv_bfloat16 g_wt_lo[768 * 256];                    // Wi^T lo
__device__ int g_done_mode;

// packed fp32x2 FMA
__device__ __forceinline__ void ffma2(u64& d, u64 a, u64 b) {
    asm("fma.rn.f32x2 %0, %1, %2, %0;" : "+l"(d) : "l"(a), "l"(b));
}
__device__ __forceinline__ float hsum2(u64 v) {
    float2 f = *reinterpret_cast<float2*>(&v);
    return f.x + f.y;
}
__device__ __forceinline__ uint32_t smem_u32(const void* p) {
    uint32_t a;
    asm("{ .reg .u64 t; cvta.to.shared.u64 t, %1; cvt.u32.u64 %0, t; }"
        : "=r"(a) : "l"(p));
    return a;
}
__device__ __forceinline__ void cp16(uint32_t s, const void* g) {
    asm volatile("cp.async.cg.shared.global [%0], [%1], 16;"
                 :: "r"(s), "l"(__cvta_generic_to_global(g)) : "memory");
}
#define LDSM4(r, addr) \
    asm volatile("ldmatrix.sync.aligned.m8n8.x4.shared.b16 {%0,%1,%2,%3}, [%4];" \
                 : "=r"((r)[0]), "=r"((r)[1]), "=r"((r)[2]), "=r"((r)[3]) : "r"(addr))
#define MMA(c, A, b0, b1) \
    asm volatile("mma.sync.aligned.m16n8k16.row.col.f32.bf16.bf16.f32 " \
                 "{%0,%1,%2,%3},{%4,%5,%6,%7},{%8,%9},{%0,%1,%2,%3};" \
                 : "+f"((c)[0]), "+f"((c)[1]), "+f"((c)[2]), "+f"((c)[3]) \
                 : "r"((A)[0]), "r"((A)[1]), "r"((A)[2]), "r"((A)[3]), \
                   "r"(b0), "r"(b1))

// ---------------------------------------------------------------------------
// Kernel 0: detect done dtype
// ---------------------------------------------------------------------------
__global__ void detect_done_kernel(const unsigned int* __restrict__ done_words)
{
    int i = blockIdx.x * blockDim.x + threadIdx.x;   // 32768 words
    if (done_words[i] > 1u) atomicOr(&g_done_mode, 1);
}

// ---------------------------------------------------------------------------
// Kernel A/B: decompose obs / Wi into bf16 hi/lo (unchanged)
// ---------------------------------------------------------------------------
__global__ void decompose_obs(const float* __restrict__ src)
{
    size_t i = (size_t)blockIdx.x * blockDim.x + threadIdx.x;  // 8388608 float4
    float4 v = ((const float4*)src)[i];
    __nv_bfloat16 h0 = __float2bfloat16(v.x);
    __nv_bfloat16 h1 = __float2bfloat16(v.y);
    __nv_bfloat16 h2 = __float2bfloat16(v.z);
    __nv_bfloat16 h3 = __float2bfloat16(v.w);
    __nv_bfloat16 l0 = __float2bfloat16(v.x - __bfloat162float(h0));
    __nv_bfloat16 l1 = __float2bfloat16(v.y - __bfloat162float(h1));
    __nv_bfloat16 l2 = __float2bfloat16(v.z - __bfloat162float(h2));
    __nv_bfloat16 l3 = __float2bfloat16(v.w - __bfloat162float(h3));
    __nv_bfloat162* hp = (__nv_bfloat162*)g_a_hi;
    __nv_bfloat162* lp = (__nv_bfloat162*)g_a_lo;
    hp[2 * i]     = __nv_bfloat162(h0, h1);
    hp[2 * i + 1] = __nv_bfloat162(h2, h3);
    lp[2 * i]     = __nv_bfloat162(l0, l1);
    lp[2 * i + 1] = __nv_bfloat162(l2, l3);
}

__global__ void decompose_wi(const float* __restrict__ Wi)
{
    int idx = blockIdx.x * blockDim.x + threadIdx.x;   // 196608
    int k = idx / 768, n = idx - k * 768;
    float w = Wi[idx];
    __nv_bfloat16 h = __float2bfloat16(w);
    __nv_bfloat16 l = __float2bfloat16(w - __bfloat162float(h));
    g_wt_hi[n * 256 + k] = h;
    g_wt_lo[n * 256 + k] = l;
}

// ---------------------------------------------------------------------------
// Kernel 1: x_proj GEMM via mma.sync bf16 hi/lo (unchanged from R6)
// ---------------------------------------------------------------------------
#define STAGE_B 40960
#define OFF_AHI 0
#define OFF_ALO 10240
#define OFF_BHI 20480
#define OFF_BLO 30720
#define XSMEM   (2 * STAGE_B)

__global__ void __launch_bounds__(256, 2)
xproj_mma_kernel(const float* __restrict__ bi)
{
    extern __shared__ char xsm[];
    const int tid = threadIdx.x, wid = tid >> 5, lane = tid & 31;
    const int warp_m = wid & 3, warp_n = wid >> 2;
    const int bN = blockIdx.x * 128;
    const int bM = blockIdx.y * 128;
    const uint32_t sb = smem_u32(xsm);

    const int grp = lane >> 3, r = lane & 7;
    uint32_t aoff[2], boff[4];
#pragma unroll
    for (int mt = 0; mt < 2; mt++)
        aoff[mt] = (uint32_t)((warp_m * 32 + mt * 16 + (grp & 1) * 8 + r) * 80
                              + (grp >> 1) * 16);
#pragma unroll
    for (int np = 0; np < 4; np++)
        boff[np] = (uint32_t)((warp_n * 64 + np * 16 + (grp >> 1) * 8 + r) * 80
                              + (grp & 1) * 16);

    const int c0row = tid >> 2, c0kc = tid & 3;
    const int c1row = (tid + 256) >> 2, c1kc = (tid + 256) & 3;

    auto load_stage = [&](int ks, int buf) {
        const uint32_t s = sb + buf * STAGE_B;
        const int k0 = ks * 32;
        {
            uint32_t so = c0row * 80 + c0kc * 16;
            size_t ga = (size_t)(bM + c0row) * 256 + k0 + c0kc * 8;
            size_t gb = (size_t)(bN + c0row) * 256 + k0 + c0kc * 8;
            cp16(s + OFF_AHI + so, g_a_hi + ga);
            cp16(s + OFF_ALO + so, g_a_lo + ga);
            cp16(s + OFF_BHI + so, g_wt_hi + gb);
            cp16(s + OFF_BLO + so, g_wt_lo + gb);
        }
        {
            uint32_t so = c1row * 80 + c1kc * 16;
            size_t ga = (size_t)(bM + c1row) * 256 + k0 + c1kc * 8;
            size_t gb = (size_t)(bN + c1row) * 256 + k0 + c1kc * 8;
            cp16(s + OFF_AHI + so, g_a_hi + ga);
            cp16(s + OFF_ALO + so, g_a_lo + ga);
            cp16(s + OFF_BHI + so, g_wt_hi + gb);
            cp16(s + OFF_BLO + so, g_wt_lo + gb);
        }
        asm volatile("cp.async.commit_group;" ::: "memory");
    };

    float acc[2][8][4];
#pragma unroll
    for (int mt = 0; mt < 2; mt++)
#pragma unroll
        for (int nt = 0; nt < 8; nt++)
#pragma unroll
            for (int e = 0; e < 4; e++) acc[mt][nt][e] = 0.f;

    load_stage(0, 0);
    load_stage(1, 1);

#pragma unroll 1
    for (int ks = 0; ks < 8; ks++) {
        if (ks < 7)
            asm volatile("cp.async.wait_group 1;" ::: "memory");
        else
            asm volatile("cp.async.wait_group 0;" ::: "memory");
        __syncthreads();

        const uint32_t s = sb + (ks & 1) * STAGE_B;
#pragma unroll
        for (int h = 0; h < 2; h++) {
            uint32_t a[2][2][4];
#pragma unroll
            for (int mt = 0; mt < 2; mt++) {
                LDSM4(a[0][mt], s + OFF_AHI + aoff[mt] + h * 32);
                LDSM4(a[1][mt], s + OFF_ALO + aoff[mt] + h * 32);
            }
#pragma unroll
            for (int np = 0; np < 4; np++) {
                uint32_t bh[4], bl[4];
                LDSM4(bh, s + OFF_BHI + boff[np] + h * 32);
                LDSM4(bl, s + OFF_BLO + boff[np] + h * 32);
#pragma unroll
                for (int mt = 0; mt < 2; mt++) {
                    MMA(acc[mt][2 * np],     a[0][mt], bh[0], bh[1]);
                    MMA(acc[mt][2 * np + 1], a[0][mt], bh[2], bh[3]);
                    MMA(acc[mt][2 * np],     a[0][mt], bl[0], bl[1]);
                    MMA(acc[mt][2 * np + 1], a[0][mt], bl[2], bl[3]);
                    MMA(acc[mt][2 * np],     a[1][mt], bh[0], bh[1]);
                    MMA(acc[mt][2 * np + 1], a[1][mt], bh[2], bh[3]);
                }
            }
        }
        __syncthreads();
        if (ks + 2 < 8) load_stage(ks + 2, ks & 1);
    }

    const int tq = lane >> 2, tr = lane & 3;
#pragma unroll
    for (int mt = 0; mt < 2; mt++) {
#pragma unroll
        for (int nt = 0; nt < 8; nt++) {
            int row = bM + warp_m * 32 + mt * 16 + tq;
            int col = bN + warp_n * 64 + nt * 8 + tr * 2;
            float2 bb = *(const float2*)(bi + col);
            float2 o0 = make_float2(acc[mt][nt][0] + bb.x, acc[mt][nt][1] + bb.y);
            float2 o1 = make_float2(acc[mt][nt][2] + bb.x, acc[mt][nt][3] + bb.y);
            *(float2*)(g_xproj + (size_t)row * 768 + col)       = o0;
            *(float2*)(g_xproj + (size_t)(row + 8) * 768 + col) = o1;
        }
    }
}

// ---------------------------------------------------------------------------
// Kernel 2: GRU scan. Changes vs R4:
//  - dot threads register-cache W row floats [0:96) (24x16B)
//  - x/done prefetched into registers, issued between cluster arrive & wait
//  - xs/done_s smem staging removed
// ---------------------------------------------------------------------------
#define WREG_CHUNKS 24   // 24 x 16B = 96 floats cached in registers

__device__ __forceinline__ float fsigmoid(float x) {
    return __fdividef(1.f, 1.f + __expf(-x));
}
__device__ __forceinline__ float ftanh(float x) {
    return __fdividef(2.f, 1.f + __expf(-2.f * x)) - 1.f;
}

extern __shared__ float smem[];

__global__ void __launch_bounds__(256, 1) __cluster_dims__(4, 1, 1)
scan_kernel(const void* __restrict__ done_raw,
            const float* __restrict__ init_h,
            const float* __restrict__ Wh_rz,
            const float* __restrict__ Wh_n,
            const float* __restrict__ bh_n,
            float* __restrict__ out)
{
    float* W_s   = smem;                       // [192][WPAD]
    float* hbuf  = W_s + 192 * WPAD;           // [2][4][256]
    float* accs  = hbuf + 2 * 4 * 256;         // [192][4]
    float* bhn_s = accs + 192 * 4;             // [64]

    const int tid  = threadIdx.x;
    const int rank = blockIdx.x & 3;
    const int cl   = blockIdx.x >> 2;
    const int b0   = cl * 4;

    const int done_mode = g_done_mode;
    const int* done_i32 = (const int*)done_raw;
    const unsigned char* done_u8 = (const unsigned char*)done_raw;

    // --- load weight slice (transposed into [col][k], pad WPAD) ---
    for (int idx = tid; idx < 192 * 256; idx += 256) {
        int k = idx / 192;
        int c = idx - k * 192;
        float v;
        if (c < 128) {
            int scol = (c < 64) ? (rank * 64 + c) : (256 + rank * 64 + (c - 64));
            v = Wh_rz[(size_t)k * 512 + scol];
        } else {
            v = Wh_n[(size_t)k * 256 + rank * 64 + (c - 128)];
        }
        W_s[c * WPAD + k] = v;
    }
    if (tid < 64) bhn_s[tid] = bh_n[rank * 64 + tid];

    for (int idx = tid; idx < 4 * 256; idx += 256)
        hbuf[idx] = init_h[(size_t)(b0 + (idx >> 8)) * Hsz + (idx & 255)];
    __syncthreads();

    // --- register-cache first 96 floats of this dot thread's W row ---
    ulonglong2 Wreg[WREG_CHUNKS];
    const ulonglong2* Wc = (const ulonglong2*)(W_s + (tid < 192 ? tid : 0) * WPAD);
    if (tid < 192) {
#pragma unroll
        for (int q = 0; q < WREG_CHUNKS; q++) Wreg[q] = Wc[q];
    }

    uint32_t hbuf_u32 = smem_u32(hbuf);

    // elementwise-thread identity + x/done prefetch state
    const int g  = tid >> 6;
    const int j  = tid & 63;
    const int jg = rank * 64 + j;
    const float bhn = bhn_s[j];
    const float* xbase = g_xproj + (size_t)(b0 + g) * Tsz * 768 + jg;
    const size_t done_base = (size_t)(b0 + g) * Tsz;

    float xr = __ldg(xbase);
    float xz = __ldg(xbase + 256);
    float xn = __ldg(xbase + 512);
    int dn = done_mode ? (int)done_u8[done_base] : done_i32[done_base];

    float* ys = out + Bsz * Hsz;
    int p = 0;

    for (int t = 0; t < Tsz; t++) {
        if (tid < 192) {
            const ulonglong2* hb = (const ulonglong2*)(hbuf + p * 1024);
            u64 a0l = 0, a0h = 0, a1l = 0, a1h = 0;
            u64 a2l = 0, a2h = 0, a3l = 0, a3h = 0;
#pragma unroll
            for (int kq = 0; kq < WREG_CHUNKS; kq++) {
                ulonglong2 w  = Wreg[kq];
                ulonglong2 h0 = hb[kq];
                ffma2(a0l, w.x, h0.x); ffma2(a0h, w.y, h0.y);
                ulonglong2 h1 = hb[64 + kq];
                ffma2(a1l, w.x, h1.x); ffma2(a1h, w.y, h1.y);
                ulonglong2 h2 = hb[128 + kq];
                ffma2(a2l, w.x, h2.x); ffma2(a2h, w.y, h2.y);
                ulonglong2 h3 = hb[192 + kq];
                ffma2(a3l, w.x, h3.x); ffma2(a3h, w.y, h3.y);
            }
#pragma unroll 4
            for (int kq = WREG_CHUNKS; kq < 64; kq++) {
                ulonglong2 w  = Wc[kq];
                ulonglong2 h0 = hb[kq];
                ffma2(a0l, w.x, h0.x); ffma2(a0h, w.y, h0.y);
                ulonglong2 h1 = hb[64 + kq];
                ffma2(a1l, w.x, h1.x); ffma2(a1h, w.y, h1.y);
                ulonglong2 h2 = hb[128 + kq];
                ffma2(a2l, w.x, h2.x); ffma2(a2h, w.y, h2.y);
                ulonglong2 h3 = hb[192 + kq];
                ffma2(a3l, w.x, h3.x); ffma2(a3h, w.y, h3.y);
            }
            ((float4*)accs)[tid] = make_float4(hsum2(a0l) + hsum2(a0h),
                                               hsum2(a1l) + hsum2(a1h),
                                               hsum2(a2l) + hsum2(a2h),
                                               hsum2(a3l) + hsum2(a3h));
        }
        __syncthreads();

        {
            float hr = accs[j * 4 + g];
            float hz = accs[(64 + j) * 4 + g];
            float hn = accs[(128 + j) * 4 + g];
            float hcur = hbuf[p * 1024 + g * 256 + jg];
            if (dn) { hr = 0.f; hz = 0.f; hn = 0.f; hcur = 0.f; }
            float r = fsigmoid(xr + hr);
            float z = fsigmoid(xz + hz);
            float n = ftanh(xn + r * (hn + bhn));
            float hnew = n + z * (hcur - n);

            ys[((size_t)(b0 + g) * Tsz + t) * Hsz + jg] = hnew;
            if (t == Tsz - 1) out[(b0 + g) * Hsz + jg] = hnew;

            // broadcast h_new to all 4 cluster CTAs' next-phase buffer
            uint32_t la = hbuf_u32 + (uint32_t)(((1 - p) * 1024 + g * 256 + jg) * 4);
#pragma unroll
            for (uint32_t dst = 0; dst < 4; dst++) {
                uint32_t ra;
                asm volatile("mapa.shared::cluster.u32 %0, %1, %2;"
                             : "=r"(ra) : "r"(la), "r"(dst));
                asm volatile("st.shared::cluster.f32 [%0], %1;"
                             :: "r"(ra), "f"(hnew) : "memory");
            }
        }

        asm volatile("barrier.cluster.arrive.aligned;" ::: "memory");
        // prefetch next step's x + done under the barrier wait + LDG latency
        if (t + 1 < Tsz) {
            const float* xp = xbase + (size_t)(t + 1) * 768;
            xr = __ldg(xp);
            xz = __ldg(xp + 256);
            xn = __ldg(xp + 512);
            size_t di = done_base + t + 1;
            dn = done_mode ? (int)done_u8[di] : done_i32[di];
        }
        asm volatile("barrier.cluster.wait.aligned;" ::: "memory");
        p ^= 1;
    }
}

// ---------------------------------------------------------------------------
// Launch
// ---------------------------------------------------------------------------
static const int SCAN_SMEM_BYTES =
    (192 * WPAD + 2 * 4 * 256 + 192 * 4 + 64) * 4;

extern "C" void kernel_launch(void* const* d_in, const int* in_sizes, int n_in,
                              void* d_out, int out_size)
{
    (void)in_sizes; (void)n_in; (void)out_size;
    const float* obs    = (const float*)d_in[0];
    const void*  done   = d_in[1];
    const float* init_h = (const float*)d_in[2];
    const float* Wi     = (const float*)d_in[3];
    const float* bi     = (const float*)d_in[4];
    const float* Wh_rz  = (const float*)d_in[5];
    const float* Wh_n   = (const float*)d_in[6];
    const float* bh_n   = (const float*)d_in[7];
    float* out = (float*)d_out;

    cudaFuncSetAttribute(scan_kernel, cudaFuncAttributeMaxDynamicSharedMemorySize,
                         SCAN_SMEM_BYTES);
    cudaFuncSetAttribute(xproj_mma_kernel, cudaFuncAttributeMaxDynamicSharedMemorySize,
                         XSMEM);

    detect_done_kernel<<<128, 256>>>((const unsigned int*)done);
    decompose_obs<<<32768, 256>>>(obs);
    decompose_wi<<<768, 256>>>(Wi);

    dim3 ggrid(6, 1024);
    xproj_mma_kernel<<<ggrid, 256, XSMEM>>>(bi);

    scan_kernel<<<128, 256, SCAN_SMEM_BYTES>>>(done, init_h, Wh_rz, Wh_n, bh_n, out);
}

// round 8
// speedup vs baseline: 2.2964x; 1.0486x over previous
#include <cuda_runtime.h>
#include <cuda_bf16.h>
#include <cstdint>

#define Bsz 128
#define Tsz 1024
#define Dsz 256
#define Hsz 256
#define WPAD 260

typedef unsigned long long u64;

// ---------------- scratch (__device__ globals; no runtime alloc) ----------
__device__ float g_xproj[(size_t)Bsz * Tsz * 3 * Hsz];          // [B*T,768]
__device__ __nv_bfloat16 g_a_hi[(size_t)Bsz * Tsz * Dsz];       // obs hi
__device__ __nv_bfloat16 g_a_lo[(size_t)Bsz * Tsz * Dsz];       // obs lo
__device__ __nv_bfloat16 g_wt_hi[768 * 256];                    // Wi^T hi [n][k]
__device__ __nv_bfloat16 g_wt_lo[768 * 256];                    // Wi^T lo
__device__ int g_done_mode;

// packed fp32x2 FMA
__device__ __forceinline__ void ffma2(u64& d, u64 a, u64 b) {
    asm("fma.rn.f32x2 %0, %1, %2, %0;" : "+l"(d) : "l"(a), "l"(b));
}
__device__ __forceinline__ float hsum2(u64 v) {
    float2 f = *reinterpret_cast<float2*>(&v);
    return f.x + f.y;
}
__device__ __forceinline__ uint32_t smem_u32(const void* p) {
    uint32_t a;
    asm("{ .reg .u64 t; cvta.to.shared.u64 t, %1; cvt.u32.u64 %0, t; }"
        : "=r"(a) : "l"(p));
    return a;
}
__device__ __forceinline__ void cp16(uint32_t s, const void* g) {
    asm volatile("cp.async.cg.shared.global [%0], [%1], 16;"
                 :: "r"(s), "l"(__cvta_generic_to_global(g)) : "memory");
}
#define LDSM4(r, addr) \
    asm volatile("ldmatrix.sync.aligned.m8n8.x4.shared.b16 {%0,%1,%2,%3}, [%4];" \
                 : "=r"((r)[0]), "=r"((r)[1]), "=r"((r)[2]), "=r"((r)[3]) : "r"(addr))
#define MMA(c, A, b0, b1) \
    asm volatile("mma.sync.aligned.m16n8k16.row.col.f32.bf16.bf16.f32 " \
                 "{%0,%1,%2,%3},{%4,%5,%6,%7},{%8,%9},{%0,%1,%2,%3};" \
                 : "+f"((c)[0]), "+f"((c)[1]), "+f"((c)[2]), "+f"((c)[3]) \
                 : "r"((A)[0]), "r"((A)[1]), "r"((A)[2]), "r"((A)[3]), \
                   "r"(b0), "r"(b1))

// ---------------------------------------------------------------------------
// Kernel 0: detect done dtype
// ---------------------------------------------------------------------------
__global__ void detect_done_kernel(const unsigned int* __restrict__ done_words)
{
    int i = blockIdx.x * blockDim.x + threadIdx.x;   // 32768 words
    if (done_words[i] > 1u) atomicOr(&g_done_mode, 1);
}

// ---------------------------------------------------------------------------
// Kernel A/B: decompose obs / Wi into bf16 hi/lo (unchanged)
// ---------------------------------------------------------------------------
__global__ void decompose_obs(const float* __restrict__ src)
{
    size_t i = (size_t)blockIdx.x * blockDim.x + threadIdx.x;  // 8388608 float4
    float4 v = ((const float4*)src)[i];
    __nv_bfloat16 h0 = __float2bfloat16(v.x);
    __nv_bfloat16 h1 = __float2bfloat16(v.y);
    __nv_bfloat16 h2 = __float2bfloat16(v.z);
    __nv_bfloat16 h3 = __float2bfloat16(v.w);
    __nv_bfloat16 l0 = __float2bfloat16(v.x - __bfloat162float(h0));
    __nv_bfloat16 l1 = __float2bfloat16(v.y - __bfloat162float(h1));
    __nv_bfloat16 l2 = __float2bfloat16(v.z - __bfloat162float(h2));
    __nv_bfloat16 l3 = __float2bfloat16(v.w - __bfloat162float(h3));
    __nv_bfloat162* hp = (__nv_bfloat162*)g_a_hi;
    __nv_bfloat162* lp = (__nv_bfloat162*)g_a_lo;
    hp[2 * i]     = __nv_bfloat162(h0, h1);
    hp[2 * i + 1] = __nv_bfloat162(h2, h3);
    lp[2 * i]     = __nv_bfloat162(l0, l1);
    lp[2 * i + 1] = __nv_bfloat162(l2, l3);
}

__global__ void decompose_wi(const float* __restrict__ Wi)
{
    int idx = blockIdx.x * blockDim.x + threadIdx.x;   // 196608
    int k = idx / 768, n = idx - k * 768;
    float w = Wi[idx];
    __nv_bfloat16 h = __float2bfloat16(w);
    __nv_bfloat16 l = __float2bfloat16(w - __bfloat162float(h));
    g_wt_hi[n * 256 + k] = h;
    g_wt_lo[n * 256 + k] = l;
}

// ---------------------------------------------------------------------------
// Kernel 1: x_proj GEMM via mma.sync bf16 hi/lo (unchanged from R6)
// ---------------------------------------------------------------------------
#define STAGE_B 40960
#define OFF_AHI 0
#define OFF_ALO 10240
#define OFF_BHI 20480
#define OFF_BLO 30720
#define XSMEM   (2 * STAGE_B)

__global__ void __launch_bounds__(256, 2)
xproj_mma_kernel(const float* __restrict__ bi)
{
    extern __shared__ char xsm[];
    const int tid = threadIdx.x, wid = tid >> 5, lane = tid & 31;
    const int warp_m = wid & 3, warp_n = wid >> 2;
    const int bN = blockIdx.x * 128;
    const int bM = blockIdx.y * 128;
    const uint32_t sb = smem_u32(xsm);

    const int grp = lane >> 3, r = lane & 7;
    uint32_t aoff[2], boff[4];
#pragma unroll
    for (int mt = 0; mt < 2; mt++)
        aoff[mt] = (uint32_t)((warp_m * 32 + mt * 16 + (grp & 1) * 8 + r) * 80
                              + (grp >> 1) * 16);
#pragma unroll
    for (int np = 0; np < 4; np++)
        boff[np] = (uint32_t)((warp_n * 64 + np * 16 + (grp >> 1) * 8 + r) * 80
                              + (grp & 1) * 16);

    const int c0row = tid >> 2, c0kc = tid & 3;
    const int c1row = (tid + 256) >> 2, c1kc = (tid + 256) & 3;

    auto load_stage = [&](int ks, int buf) {
        const uint32_t s = sb + buf * STAGE_B;
        const int k0 = ks * 32;
        {
            uint32_t so = c0row * 80 + c0kc * 16;
            size_t ga = (size_t)(bM + c0row) * 256 + k0 + c0kc * 8;
            size_t gb = (size_t)(bN + c0row) * 256 + k0 + c0kc * 8;
            cp16(s + OFF_AHI + so, g_a_hi + ga);
            cp16(s + OFF_ALO + so, g_a_lo + ga);
            cp16(s + OFF_BHI + so, g_wt_hi + gb);
            cp16(s + OFF_BLO + so, g_wt_lo + gb);
        }
        {
            uint32_t so = c1row * 80 + c1kc * 16;
            size_t ga = (size_t)(bM + c1row) * 256 + k0 + c1kc * 8;
            size_t gb = (size_t)(bN + c1row) * 256 + k0 + c1kc * 8;
            cp16(s + OFF_AHI + so, g_a_hi + ga);
            cp16(s + OFF_ALO + so, g_a_lo + ga);
            cp16(s + OFF_BHI + so, g_wt_hi + gb);
            cp16(s + OFF_BLO + so, g_wt_lo + gb);
        }
        asm volatile("cp.async.commit_group;" ::: "memory");
    };

    float acc[2][8][4];
#pragma unroll
    for (int mt = 0; mt < 2; mt++)
#pragma unroll
        for (int nt = 0; nt < 8; nt++)
#pragma unroll
            for (int e = 0; e < 4; e++) acc[mt][nt][e] = 0.f;

    load_stage(0, 0);
    load_stage(1, 1);

#pragma unroll 1
    for (int ks = 0; ks < 8; ks++) {
        if (ks < 7)
            asm volatile("cp.async.wait_group 1;" ::: "memory");
        else
            asm volatile("cp.async.wait_group 0;" ::: "memory");
        __syncthreads();

        const uint32_t s = sb + (ks & 1) * STAGE_B;
#pragma unroll
        for (int h = 0; h < 2; h++) {
            uint32_t a[2][2][4];
#pragma unroll
            for (int mt = 0; mt < 2; mt++) {
                LDSM4(a[0][mt], s + OFF_AHI + aoff[mt] + h * 32);
                LDSM4(a[1][mt], s + OFF_ALO + aoff[mt] + h * 32);
            }
#pragma unroll
            for (int np = 0; np < 4; np++) {
                uint32_t bh[4], bl[4];
                LDSM4(bh, s + OFF_BHI + boff[np] + h * 32);
                LDSM4(bl, s + OFF_BLO + boff[np] + h * 32);
#pragma unroll
                for (int mt = 0; mt < 2; mt++) {
                    MMA(acc[mt][2 * np],     a[0][mt], bh[0], bh[1]);
                    MMA(acc[mt][2 * np + 1], a[0][mt], bh[2], bh[3]);
                    MMA(acc[mt][2 * np],     a[0][mt], bl[0], bl[1]);
                    MMA(acc[mt][2 * np + 1], a[0][mt], bl[2], bl[3]);
                    MMA(acc[mt][2 * np],     a[1][mt], bh[0], bh[1]);
                    MMA(acc[mt][2 * np + 1], a[1][mt], bh[2], bh[3]);
                }
            }
        }
        __syncthreads();
        if (ks + 2 < 8) load_stage(ks + 2, ks & 1);
    }

    const int tq = lane >> 2, tr = lane & 3;
#pragma unroll
    for (int mt = 0; mt < 2; mt++) {
#pragma unroll
        for (int nt = 0; nt < 8; nt++) {
            int row = bM + warp_m * 32 + mt * 16 + tq;
            int col = bN + warp_n * 64 + nt * 8 + tr * 2;
            float2 bb = *(const float2*)(bi + col);
            float2 o0 = make_float2(acc[mt][nt][0] + bb.x, acc[mt][nt][1] + bb.y);
            float2 o1 = make_float2(acc[mt][nt][2] + bb.x, acc[mt][nt][3] + bb.y);
            *(float2*)(g_xproj + (size_t)row * 768 + col)       = o0;
            *(float2*)(g_xproj + (size_t)(row + 8) * 768 + col) = o1;
        }
    }
}

// ---------------------------------------------------------------------------
// Kernel 2: GRU scan. R8: 512 threads, split-K dots (12 warps, 2 halves of
// K=128 each), partial sums in accs2[2][192][4], elementwise on threads 0-255
// sums the halves. W reg-cache 12 chunks/thread. x/done prefetch under the
// cluster barrier window.
// ---------------------------------------------------------------------------
#define WREG_CHUNKS 12   // 12 x 16B = 48 floats cached in registers per thread

__device__ __forceinline__ float fsigmoid(float x) {
    return __fdividef(1.f, 1.f + __expf(-x));
}
__device__ __forceinline__ float ftanh(float x) {
    return __fdividef(2.f, 1.f + __expf(-2.f * x)) - 1.f;
}

extern __shared__ float smem[];

__global__ void __launch_bounds__(512, 1) __cluster_dims__(4, 1, 1)
scan_kernel(const void* __restrict__ done_raw,
            const float* __restrict__ init_h,
            const float* __restrict__ Wh_rz,
            const float* __restrict__ Wh_n,
            const float* __restrict__ bh_n,
            float* __restrict__ out)
{
    float* W_s   = smem;                       // [192][WPAD]
    float* hbuf  = W_s + 192 * WPAD;           // [2][4][256]
    float* accs2 = hbuf + 2 * 4 * 256;         // [2][192][4]
    float* bhn_s = accs2 + 2 * 192 * 4;        // [64]

    const int tid  = threadIdx.x;
    const int rank = blockIdx.x & 3;
    const int cl   = blockIdx.x >> 2;
    const int b0   = cl * 4;

    const int done_mode = g_done_mode;
    const int* done_i32 = (const int*)done_raw;
    const unsigned char* done_u8 = (const unsigned char*)done_raw;

    // --- load weight slice (transposed into [col][k], pad WPAD) ---
    for (int idx = tid; idx < 192 * 256; idx += 512) {
        int k = idx / 192;
        int c = idx - k * 192;
        float v;
        if (c < 128) {
            int scol = (c < 64) ? (rank * 64 + c) : (256 + rank * 64 + (c - 64));
            v = Wh_rz[(size_t)k * 512 + scol];
        } else {
            v = Wh_n[(size_t)k * 256 + rank * 64 + (c - 128)];
        }
        W_s[c * WPAD + k] = v;
    }
    if (tid < 64) bhn_s[tid] = bh_n[rank * 64 + tid];

    for (int idx = tid; idx < 4 * 256; idx += 512)
        hbuf[idx] = init_h[(size_t)(b0 + (idx >> 8)) * Hsz + (idx & 255)];
    __syncthreads();

    // dot-thread identity: threads [0,384): column c, K-half
    const bool is_dot = (tid < 384);
    const int dc   = is_dot ? (tid % 192) : 0;
    const int half = is_dot ? (tid / 192) : 0;
    const int kq0  = half * 32;

    const ulonglong2* Wc = (const ulonglong2*)(W_s + dc * WPAD) + kq0;
    ulonglong2 Wreg[WREG_CHUNKS];
    if (is_dot) {
#pragma unroll
        for (int q = 0; q < WREG_CHUNKS; q++) Wreg[q] = Wc[q];
    }

    uint32_t hbuf_u32 = smem_u32(hbuf);

    // elementwise identity (threads 0-255): batch g, column j
    const int g  = (tid >> 6) & 3;
    const int j  = tid & 63;
    const int jg = rank * 64 + j;
    const float bhn = bhn_s[j];
    const float* xbase = g_xproj + (size_t)(b0 + g) * Tsz * 768 + jg;
    const size_t done_base = (size_t)(b0 + g) * Tsz;
    const bool is_ew = (tid < 256);

    float xr = 0.f, xz = 0.f, xn = 0.f;
    int dn = 0;
    if (is_ew) {
        xr = __ldg(xbase);
        xz = __ldg(xbase + 256);
        xn = __ldg(xbase + 512);
        dn = done_mode ? (int)done_u8[done_base] : done_i32[done_base];
    }

    float* ys = out + Bsz * Hsz;
    int p = 0;

    for (int t = 0; t < Tsz; t++) {
        if (is_dot) {
            const ulonglong2* hb = (const ulonglong2*)(hbuf + p * 1024) + kq0;
            u64 a0l = 0, a0h = 0, a1l = 0, a1h = 0;
            u64 a2l = 0, a2h = 0, a3l = 0, a3h = 0;
#pragma unroll
            for (int i = 0; i < WREG_CHUNKS; i++) {
                ulonglong2 w  = Wreg[i];
                ulonglong2 h0 = hb[i];
                ffma2(a0l, w.x, h0.x); ffma2(a0h, w.y, h0.y);
                ulonglong2 h1 = hb[64 + i];
                ffma2(a1l, w.x, h1.x); ffma2(a1h, w.y, h1.y);
                ulonglong2 h2 = hb[128 + i];
                ffma2(a2l, w.x, h2.x); ffma2(a2h, w.y, h2.y);
                ulonglong2 h3 = hb[192 + i];
                ffma2(a3l, w.x, h3.x); ffma2(a3h, w.y, h3.y);
            }
#pragma unroll 5
            for (int i = WREG_CHUNKS; i < 32; i++) {
                ulonglong2 w  = Wc[i];
                ulonglong2 h0 = hb[i];
                ffma2(a0l, w.x, h0.x); ffma2(a0h, w.y, h0.y);
                ulonglong2 h1 = hb[64 + i];
                ffma2(a1l, w.x, h1.x); ffma2(a1h, w.y, h1.y);
                ulonglong2 h2 = hb[128 + i];
                ffma2(a2l, w.x, h2.x); ffma2(a2h, w.y, h2.y);
                ulonglong2 h3 = hb[192 + i];
                ffma2(a3l, w.x, h3.x); ffma2(a3h, w.y, h3.y);
            }
            ((float4*)accs2)[half * 192 + dc] =
                make_float4(hsum2(a0l) + hsum2(a0h),
                            hsum2(a1l) + hsum2(a1h),
                            hsum2(a2l) + hsum2(a2h),
                            hsum2(a3l) + hsum2(a3h));
        }
        __syncthreads();

        if (is_ew) {
            float hr = accs2[j * 4 + g]         + accs2[(192 + j) * 4 + g];
            float hz = accs2[(64 + j) * 4 + g]  + accs2[(192 + 64 + j) * 4 + g];
            float hn = accs2[(128 + j) * 4 + g] + accs2[(192 + 128 + j) * 4 + g];
            float hcur = hbuf[p * 1024 + g * 256 + jg];
            if (dn) { hr = 0.f; hz = 0.f; hn = 0.f; hcur = 0.f; }
            float r = fsigmoid(xr + hr);
            float z = fsigmoid(xz + hz);
            float n = ftanh(xn + r * (hn + bhn));
            float hnew = n + z * (hcur - n);

            ys[((size_t)(b0 + g) * Tsz + t) * Hsz + jg] = hnew;
            if (t == Tsz - 1) out[(b0 + g) * Hsz + jg] = hnew;

            // broadcast h_new into all 4 cluster CTAs' next-phase buffer
            uint32_t la = hbuf_u32 + (uint32_t)(((1 - p) * 1024 + g * 256 + jg) * 4);
#pragma unroll
            for (uint32_t dst = 0; dst < 4; dst++) {
                uint32_t ra;
                asm volatile("mapa.shared::cluster.u32 %0, %1, %2;"
                             : "=r"(ra) : "r"(la), "r"(dst));
                asm volatile("st.shared::cluster.f32 [%0], %1;"
                             :: "r"(ra), "f"(hnew) : "memory");
            }
        }

        asm volatile("barrier.cluster.arrive.aligned;" ::: "memory");
        if (is_ew && t + 1 < Tsz) {
            const float* xp = xbase + (size_t)(t + 1) * 768;
            xr = __ldg(xp);
            xz = __ldg(xp + 256);
            xn = __ldg(xp + 512);
            size_t di = done_base + t + 1;
            dn = done_mode ? (int)done_u8[di] : done_i32[di];
        }
        asm volatile("barrier.cluster.wait.aligned;" ::: "memory");
        p ^= 1;
    }
}

// ---------------------------------------------------------------------------
// Launch
// ---------------------------------------------------------------------------
static const int SCAN_SMEM_BYTES =
    (192 * WPAD + 2 * 4 * 256 + 2 * 192 * 4 + 64) * 4;

extern "C" void kernel_launch(void* const* d_in, const int* in_sizes, int n_in,
                              void* d_out, int out_size)
{
    (void)in_sizes; (void)n_in; (void)out_size;
    const float* obs    = (const float*)d_in[0];
    const void*  done   = d_in[1];
    const float* init_h = (const float*)d_in[2];
    const float* Wi     = (const float*)d_in[3];
    const float* bi     = (const float*)d_in[4];
    const float* Wh_rz  = (const float*)d_in[5];
    const float* Wh_n   = (const float*)d_in[6];
    const float* bh_n   = (const float*)d_in[7];
    float* out = (float*)d_out;

    cudaFuncSetAttribute(scan_kernel, cudaFuncAttributeMaxDynamicSharedMemorySize,
                         SCAN_SMEM_BYTES);
    cudaFuncSetAttribute(xproj_mma_kernel, cudaFuncAttributeMaxDynamicSharedMemorySize,
                         XSMEM);

    detect_done_kernel<<<128, 256>>>((const unsigned int*)done);
    decompose_obs<<<32768, 256>>>(obs);
    decompose_wi<<<768, 256>>>(Wi);

    dim3 ggrid(6, 1024);
    xproj_mma_kernel<<<ggrid, 256, XSMEM>>>(bi);

    scan_kernel<<<128, 512, SCAN_SMEM_BYTES>>>(done, init_h, Wh_rz, Wh_n, bh_n, out);
}